// round 16
// baseline (speedup 1.0000x reference)
#include <cuda_runtime.h>
#include <cuda_fp16.h>
#include <cstdint>

#define NE 8
#define DM 1024
#define DF 4096
#define NT 8192  // B*S

// CTA tile (R6 proven config)
#define TM 128
#define TN 128
#define TK 32

// SMEM layout (bytes)
#define SM_ROWTOK 0          // 128 ints
#define SM_BIAS   512        // 128 floats
#define SM_STAGE  2048
#define OFF_AH    0          // A fp16 tile: 8KB
#define OFF_BH    8192       // B fp16 (converted) tile: 8KB
#define OFF_RAW   16384      // B raw fp32 tile: 32 rows x 528B = 16896B
#define STAGE_BYTES 33792
#define NSTAGE 3
#define SMEM_TOTAL (SM_STAGE + NSTAGE * STAGE_BYTES)   // 103424 (2 CTAs/SM ok)

#define MAXTILES 72

// ---------------- static scratch ----------------
__device__ int g_cnt[NE];
__device__ int g_bucket[NE][NT];
__device__ __align__(256) __half g_xh[(size_t)NT * DM];
__device__ __align__(256) __half g_hh[(size_t)NT * DF];

// ---------------- PTX helpers ----------------
__device__ __forceinline__ uint32_t smem_u32(const void* p) {
    uint32_t a;
    asm("{ .reg .u64 t; cvta.to.shared.u64 t, %1; cvt.u32.u64 %0, t; }" : "=r"(a) : "l"(p));
    return a;
}
__device__ __forceinline__ void cp16(uint32_t dst, const void* src) {
    asm volatile("cp.async.cg.shared.global [%0], [%1], 16;" :: "r"(dst), "l"(src));
}
__device__ __forceinline__ void cp_commit() { asm volatile("cp.async.commit_group;" ::: "memory"); }
template <int N>
__device__ __forceinline__ void cp_wait() { asm volatile("cp.async.wait_group %0;" :: "n"(N) : "memory"); }

#define LDSM4(r0, r1, r2, r3, addr) \
    asm volatile("ldmatrix.sync.aligned.m8n8.x4.shared.b16 {%0,%1,%2,%3}, [%4];" \
                 : "=r"(r0), "=r"(r1), "=r"(r2), "=r"(r3) : "r"(addr))

#define MMA16816(d, a, b) \
    asm volatile("mma.sync.aligned.m16n8k16.row.col.f32.f16.f16.f32 " \
                 "{%0,%1,%2,%3},{%4,%5,%6,%7},{%8,%9},{%0,%1,%2,%3};" \
                 : "+f"((d)[0]), "+f"((d)[1]), "+f"((d)[2]), "+f"((d)[3]) \
                 : "r"((a)[0]), "r"((a)[1]), "r"((a)[2]), "r"((a)[3]), \
                   "r"((b)[0]), "r"((b)[1]))

// ---------------- routing ----------------
__global__ void zero_cnt_kernel() {
    if (threadIdx.x < NE) g_cnt[threadIdx.x] = 0;
}

__global__ void gate_route_kernel(const float* __restrict__ x,
                                  const float* __restrict__ gw,
                                  const float* __restrict__ gb) {
    int gtid = blockIdx.x * blockDim.x + threadIdx.x;
    int tok = gtid >> 5;
    int lane = gtid & 31;
    if (tok >= NT) return;
    const float* xr = x + (size_t)tok * DM;
    float acc[NE];
#pragma unroll
    for (int e = 0; e < NE; e++) acc[e] = 0.f;
    for (int d = lane; d < DM; d += 32) {
        float xv = xr[d];
        const float4* g4 = reinterpret_cast<const float4*>(gw + (size_t)d * NE);
        float4 a = g4[0], b = g4[1];
        acc[0] += xv * a.x; acc[1] += xv * a.y; acc[2] += xv * a.z; acc[3] += xv * a.w;
        acc[4] += xv * b.x; acc[5] += xv * b.y; acc[6] += xv * b.z; acc[7] += xv * b.w;
    }
#pragma unroll
    for (int e = 0; e < NE; e++) {
#pragma unroll
        for (int off = 16; off > 0; off >>= 1)
            acc[e] += __shfl_down_sync(0xffffffffu, acc[e], off);
    }
    if (lane == 0) {
        int best = 0;
        float bv = acc[0] + gb[0];
#pragma unroll
        for (int e = 1; e < NE; e++) {
            float v = acc[e] + gb[e];
            if (v > bv) { bv = v; best = e; }
        }
        int pos = atomicAdd(&g_cnt[best], 1);
        g_bucket[best][pos] = tok;
    }
}

// ---------------- fp32 -> fp16 (x only) ----------------
__global__ void xconv_kernel(const float* __restrict__ x,
                             __half* __restrict__ h, int n4) {
    for (int i = blockIdx.x * blockDim.x + threadIdx.x; i < n4; i += gridDim.x * blockDim.x) {
        float4 v = reinterpret_cast<const float4*>(x)[i];
        __half2 h0, h1;
        h0.x = __float2half(v.x); h0.y = __float2half(v.y);
        h1.x = __float2half(v.z); h1.y = __float2half(v.w);
        uint2 pk;
        pk.x = *reinterpret_cast<uint32_t*>(&h0);
        pk.y = *reinterpret_cast<uint32_t*>(&h1);
        reinterpret_cast<uint2*>(h)[i] = pk;
    }
}

// swizzled smem byte offset within a [rows x 32] fp16 array (64B rows, 4 chunks)
__device__ __forceinline__ uint32_t sw_off(int row, int chunk) {
    return (uint32_t)(row * 64 + ((chunk ^ ((row >> 1) & 3)) << 4));
}

// ---------------- HMMA grouped GEMM w/ in-kernel B conversion ----------------
// B source: W fp32 [e][KDIM][NDIM]; converted per-stage to swizzled fp16 [n][k]
template <int KDIM, int NDIM, bool RELU_H>
__global__ __launch_bounds__(256, 2)
void moe_mma_kernel(const __half* __restrict__ A,
                    const float* __restrict__ Wf,
                    const float* __restrict__ bias,
                    __half* __restrict__ OutH,
                    float* __restrict__ OutF) {
    extern __shared__ __align__(1024) char smem[];
    // derive (e, m0) from counts — no tile_plan kernel
    const int ty = blockIdx.y;
    int e = -1, m0 = 0, acc_t = 0;
#pragma unroll
    for (int ee = 0; ee < NE; ee++) {
        int c = g_cnt[ee];
        int nt = (c + TM - 1) / TM;
        if (e < 0 && ty < acc_t + nt) { e = ee; m0 = (ty - acc_t) * TM; }
        acc_t += nt;
    }
    if (e < 0) return;
    const int mcnt = g_cnt[e];
    const int n0 = blockIdx.x * TN;
    const int tid = threadIdx.x;
    const uint32_t sb = smem_u32(smem);

    int* rowtok = (int*)(smem + SM_ROWTOK);
    float* bias_s = (float*)(smem + SM_BIAS);
    if (tid < TM) {
        int gm = m0 + tid;
        rowtok[tid] = g_bucket[e][gm < mcnt ? gm : m0];
        bias_s[tid] = bias[(size_t)e * NDIM + n0 + tid];
    }
    __syncthreads();

    // ---- A loader: thread t -> row t>>1, chunks (t&1)*2 + {0,1} ----
    const int ldr = tid >> 1;
    const int ldc = (tid & 1) * 2;
    const int atok = rowtok[ldr];
    const __half* aSrc = A + (size_t)atok * KDIM + ldc * 8;
    const uint32_t d0 = sw_off(ldr, ldc);
    const uint32_t d1 = sw_off(ldr, ldc + 1);
    // ---- raw B loader: thread t -> k-row t>>3, 64B seg (t&7) ----
    const int bkr = tid >> 3;
    const int bseg = tid & 7;
    const float* bSrcF = Wf + (size_t)e * KDIM * NDIM + (size_t)bkr * NDIM + n0 + bseg * 16;
    const uint32_t rawDst = (uint32_t)(bkr * 528 + bseg * 64);

    constexpr int NST = KDIM / TK;

    auto load_stage = [&](int s) {
        const uint32_t base = sb + SM_STAGE + (s % NSTAGE) * STAGE_BYTES;
        const int k0 = s * TK;
        cp16(base + OFF_AH + d0, aSrc + k0);
        cp16(base + OFF_AH + d1, aSrc + k0 + 8);
        const float* bs = bSrcF + (size_t)k0 * NDIM;
        const uint32_t rb = base + OFF_RAW + rawDst;
        cp16(rb,      bs);
        cp16(rb + 16, bs + 4);
        cp16(rb + 32, bs + 8);
        cp16(rb + 48, bs + 12);
        cp_commit();
    };

    // converter: thread t -> out row n = t>>1, k-half (t&1) (16 k values)
    auto convert_stage = [&](int s) {
        const uint32_t base = sb + SM_STAGE + (s % NSTAGE) * STAGE_BYTES;
        const uint32_t rb = base + OFF_RAW + (uint32_t)((tid & 1) * 16 * 528 + (tid >> 1) * 4);
        float f[16];
#pragma unroll
        for (int i = 0; i < 16; i++) {
            asm volatile("ld.shared.f32 %0, [%1];" : "=f"(f[i]) : "r"(rb + i * 528));
        }
        uint32_t hv[8];
#pragma unroll
        for (int i = 0; i < 8; i++) {
            __half2 p = __floats2half2_rn(f[2 * i], f[2 * i + 1]);
            hv[i] = *reinterpret_cast<uint32_t*>(&p);
        }
        asm volatile("st.shared.v4.b32 [%0], {%1,%2,%3,%4};"
                     :: "r"(base + OFF_BH + d0), "r"(hv[0]), "r"(hv[1]), "r"(hv[2]), "r"(hv[3]));
        asm volatile("st.shared.v4.b32 [%0], {%1,%2,%3,%4};"
                     :: "r"(base + OFF_BH + d1), "r"(hv[4]), "r"(hv[5]), "r"(hv[6]), "r"(hv[7]));
    };

    // ---- mma mapping: 2x4 warp grid, warp tile 64x32 ----
    const int wid = tid >> 5;
    const int lane = tid & 31;
    const int warp_m = wid >> 2;          // 0..1
    const int warp_n = wid & 3;           // 0..3
    const int rA = warp_m * 64 + (lane & 15);
    const int rB = warp_n * 32 + (lane & 15);
    const int csel = lane >> 4;
    const int sA = (rA >> 1) & 3;
    const int sB = (rB >> 1) & 3;

    float acc[4][4][4];
#pragma unroll
    for (int i = 0; i < 4; i++)
#pragma unroll
        for (int j = 0; j < 4; j++)
#pragma unroll
            for (int r = 0; r < 4; r++) acc[i][j][r] = 0.f;

    load_stage(0);
    load_stage(1);
    cp_wait<1>();
    __syncthreads();          // all threads' stage-0 cp.async visible
    convert_stage(0);
    __syncthreads();          // converted BH(0) visible to MMA

    for (int s = 0; s < NST; s++) {
        if (s + 2 < NST) load_stage(s + 2);

        const uint32_t base = sb + SM_STAGE + (s % NSTAGE) * STAGE_BYTES;
#pragma unroll
        for (int ks = 0; ks < 2; ks++) {
            const int c0 = ks * 2;
            uint32_t ah[4][4], bh[4][2];
#pragma unroll
            for (int mt = 0; mt < 4; mt++) {
                uint32_t ad = base + OFF_AH + (uint32_t)((rA + mt * 16) * 64) +
                              (uint32_t)(((c0 + csel) ^ sA) << 4);
                LDSM4(ah[mt][0], ah[mt][1], ah[mt][2], ah[mt][3], ad);
            }
#pragma unroll
            for (int np = 0; np < 2; np++) {
                uint32_t bd = base + OFF_BH + (uint32_t)((rB + np * 16) * 64) +
                              (uint32_t)(((c0 + csel) ^ sB) << 4);
                uint32_t t0, t1, t2, t3;
                LDSM4(t0, t1, t2, t3, bd);
                bh[2 * np][0] = t0; bh[2 * np + 1][0] = t1;
                bh[2 * np][1] = t2; bh[2 * np + 1][1] = t3;
            }
#pragma unroll
            for (int mt = 0; mt < 4; mt++)
#pragma unroll
                for (int nt = 0; nt < 4; nt++)
                    MMA16816(acc[mt][nt], ah[mt], bh[nt]);
        }

        if (s + 1 < NST) {
            if (s + 2 < NST) cp_wait<1>(); else cp_wait<0>();
            __syncthreads();      // RACE FIX: other threads' raw(s+1) cp.async visible
            convert_stage(s + 1);
        }
        __syncthreads();          // converted BH(s+1) visible before next MMA
    }

    // ---- epilogue ----
#pragma unroll
    for (int mt = 0; mt < 4; mt++) {
        const int row0 = warp_m * 64 + mt * 16 + (lane >> 2);
#pragma unroll
        for (int h = 0; h < 2; h++) {
            const int lrow = row0 + 8 * h;
            if (m0 + lrow >= mcnt) continue;
            const int tok = rowtok[lrow];
#pragma unroll
            for (int nt = 0; nt < 4; nt++) {
                const int col = warp_n * 32 + nt * 8 + (lane & 3) * 2;
                float v0 = acc[mt][nt][2 * h] + bias_s[col];
                float v1 = acc[mt][nt][2 * h + 1] + bias_s[col + 1];
                const size_t o = (size_t)tok * NDIM + n0 + col;
                if (RELU_H) {
                    v0 = fmaxf(v0, 0.f);
                    v1 = fmaxf(v1, 0.f);
                    __half2 hv;
                    hv.x = __float2half(v0);
                    hv.y = __float2half(v1);
                    *reinterpret_cast<__half2*>(OutH + o) = hv;
                } else {
                    float2 f2 = make_float2(v0, v1);
                    *reinterpret_cast<float2*>(OutF + o) = f2;
                }
            }
        }
    }
}

// ---------------- launch (no weight-conversion kernels) ----------------
extern "C" void kernel_launch(void* const* d_in, const int* in_sizes, int n_in,
                              void* d_out, int out_size) {
    const float* x  = (const float*)d_in[0];
    const float* w1 = (const float*)d_in[1];
    const float* b1 = (const float*)d_in[2];
    const float* w2 = (const float*)d_in[3];
    const float* b2 = (const float*)d_in[4];
    const float* gw = (const float*)d_in[5];
    const float* gb = (const float*)d_in[6];
    float* out = (float*)d_out;

    cudaFuncSetAttribute(moe_mma_kernel<DM, DF, true>,
                         cudaFuncAttributeMaxDynamicSharedMemorySize, SMEM_TOTAL);
    cudaFuncSetAttribute(moe_mma_kernel<DF, DM, false>,
                         cudaFuncAttributeMaxDynamicSharedMemorySize, SMEM_TOTAL);

    __half *xh, *hh;
    cudaGetSymbolAddress((void**)&xh, g_xh);
    cudaGetSymbolAddress((void**)&hh, g_hh);

    cudaStream_t sA;
    cudaStreamCreateWithFlags(&sA, cudaStreamNonBlocking);
    cudaEvent_t evRoot, evX;
    cudaEventCreateWithFlags(&evRoot, cudaEventDisableTiming);
    cudaEventCreateWithFlags(&evX, cudaEventDisableTiming);

    cudaEventRecord(evRoot, 0);
    cudaStreamWaitEvent(sA, evRoot, 0);

    // main: routing  |  side A: x conversion (parallel)
    zero_cnt_kernel<<<1, 32>>>();
    gate_route_kernel<<<(NT * 32 + 255) / 256, 256>>>(x, gw, gb);
    xconv_kernel<<<2048, 256, 0, sA>>>(x, xh, NT * DM / 4);
    cudaEventRecord(evX, sA);

    // GEMM1: h = relu(x @ w1 + b1)  (converts w1 in-kernel)
    cudaStreamWaitEvent(0, evX, 0);
    moe_mma_kernel<DM, DF, true>
        <<<dim3(DF / TN, MAXTILES, 1), 256, SMEM_TOTAL>>>(xh, w1, b1, hh, nullptr);

    // GEMM2: out = h @ w2 + b2  (converts w2 in-kernel)
    moe_mma_kernel<DF, DM, false>
        <<<dim3(DM / TN, MAXTILES, 1), 256, SMEM_TOTAL>>>(hh, w2, b2, nullptr, out);

    cudaEventDestroy(evRoot);
    cudaEventDestroy(evX);
    cudaStreamDestroy(sA);
}

// round 17
// speedup vs baseline: 1.3889x; 1.3889x over previous
#include <cuda_runtime.h>
#include <cuda_fp16.h>
#include <cstdint>

#define NE 8
#define DM 1024
#define DF 4096
#define NT 8192  // B*S

// CTA tile (R6 proven config)
#define TM 128
#define TN 128
#define TK 32

// SMEM layout (bytes)
#define SM_ROWTOK 0          // 128 ints
#define SM_BIAS   512        // 128 floats
#define SM_STAGE  2048
#define OFF_AH    0
#define OFF_BH    8192
#define STAGE_BYTES 16384
#define NSTAGE 4
#define SMEM_TOTAL (SM_STAGE + NSTAGE * STAGE_BYTES)   // 67584

#define MAXTILES 72

// ---------------- static scratch ----------------
__device__ int g_cnt[NE];
__device__ int g_bucket[NE][NT];
__device__ __align__(256) __half g_xh[(size_t)NT * DM];
__device__ __align__(256) __half g_hh[(size_t)NT * DF];
__device__ __align__(256) __half g_w1h[(size_t)NE * DF * DM];   // [e][n][k]
__device__ __align__(256) __half g_w2h[(size_t)NE * DM * DF];   // [e][n][k]

// ---------------- PTX helpers ----------------
__device__ __forceinline__ uint32_t smem_u32(const void* p) {
    uint32_t a;
    asm("{ .reg .u64 t; cvta.to.shared.u64 t, %1; cvt.u32.u64 %0, t; }" : "=r"(a) : "l"(p));
    return a;
}
__device__ __forceinline__ void cp16(uint32_t dst, const void* src) {
    asm volatile("cp.async.cg.shared.global [%0], [%1], 16;" :: "r"(dst), "l"(src));
}
__device__ __forceinline__ void cp_commit() { asm volatile("cp.async.commit_group;" ::: "memory"); }
template <int N>
__device__ __forceinline__ void cp_wait() { asm volatile("cp.async.wait_group %0;" :: "n"(N) : "memory"); }

#define LDSM4(r0, r1, r2, r3, addr) \
    asm volatile("ldmatrix.sync.aligned.m8n8.x4.shared.b16 {%0,%1,%2,%3}, [%4];" \
                 : "=r"(r0), "=r"(r1), "=r"(r2), "=r"(r3) : "r"(addr))

#define MMA16816(d, a, b) \
    asm volatile("mma.sync.aligned.m16n8k16.row.col.f32.f16.f16.f32 " \
                 "{%0,%1,%2,%3},{%4,%5,%6,%7},{%8,%9},{%0,%1,%2,%3};" \
                 : "+f"((d)[0]), "+f"((d)[1]), "+f"((d)[2]), "+f"((d)[3]) \
                 : "r"((a)[0]), "r"((a)[1]), "r"((a)[2]), "r"((a)[3]), \
                   "r"((b)[0]), "r"((b)[1]))

// ---------------- routing ----------------
__global__ void zero_cnt_kernel() {
    if (threadIdx.x < NE) g_cnt[threadIdx.x] = 0;
}

__global__ void gate_route_kernel(const float* __restrict__ x,
                                  const float* __restrict__ gw,
                                  const float* __restrict__ gb) {
    int gtid = blockIdx.x * blockDim.x + threadIdx.x;
    int tok = gtid >> 5;
    int lane = gtid & 31;
    if (tok >= NT) return;
    const float* xr = x + (size_t)tok * DM;
    float acc[NE];
#pragma unroll
    for (int e = 0; e < NE; e++) acc[e] = 0.f;
    for (int d = lane; d < DM; d += 32) {
        float xv = xr[d];
        const float4* g4 = reinterpret_cast<const float4*>(gw + (size_t)d * NE);
        float4 a = g4[0], b = g4[1];
        acc[0] += xv * a.x; acc[1] += xv * a.y; acc[2] += xv * a.z; acc[3] += xv * a.w;
        acc[4] += xv * b.x; acc[5] += xv * b.y; acc[6] += xv * b.z; acc[7] += xv * b.w;
    }
#pragma unroll
    for (int e = 0; e < NE; e++) {
#pragma unroll
        for (int off = 16; off > 0; off >>= 1)
            acc[e] += __shfl_down_sync(0xffffffffu, acc[e], off);
    }
    if (lane == 0) {
        int best = 0;
        float bv = acc[0] + gb[0];
#pragma unroll
        for (int e = 1; e < NE; e++) {
            float v = acc[e] + gb[e];
            if (v > bv) { bv = v; best = e; }
        }
        int pos = atomicAdd(&g_cnt[best], 1);
        g_bucket[best][pos] = tok;
    }
}

// ---------------- fp32 -> fp16 ----------------
__global__ void xconv_kernel(const float* __restrict__ x,
                             __half* __restrict__ h, int n4) {
    for (int i = blockIdx.x * blockDim.x + threadIdx.x; i < n4; i += gridDim.x * blockDim.x) {
        float4 v = reinterpret_cast<const float4*>(x)[i];
        __half2 h0, h1;
        h0.x = __float2half(v.x); h0.y = __float2half(v.y);
        h1.x = __float2half(v.z); h1.y = __float2half(v.w);
        uint2 pk;
        pk.x = *reinterpret_cast<uint32_t*>(&h0);
        pk.y = *reinterpret_cast<uint32_t*>(&h1);
        reinterpret_cast<uint2*>(h)[i] = pk;
    }
}

// W [e][K][N] fp32 -> Wh [e][N][K] fp16 (tiled transpose + round)
__global__ void wconv_kernel(const float* __restrict__ W,
                             __half* __restrict__ Wh, int K, int N) {
    __shared__ float ts[32][65];
    int e = blockIdx.z, n0 = blockIdx.x * 64, k0 = blockIdx.y * 32;
    const float* Wp = W + (size_t)e * K * N;
#pragma unroll
    for (int i = 0; i < 2; i++) {
        int idx = threadIdx.x + 256 * i;      // 512 float4 slots
        int k = idx >> 4, n4 = idx & 15;
        float4 v = *reinterpret_cast<const float4*>(Wp + (size_t)(k0 + k) * N + n0 + n4 * 4);
        ts[k][n4 * 4 + 0] = v.x;
        ts[k][n4 * 4 + 1] = v.y;
        ts[k][n4 * 4 + 2] = v.z;
        ts[k][n4 * 4 + 3] = v.w;
    }
    __syncthreads();
#pragma unroll
    for (int i = 0; i < 2; i++) {
        int idx = threadIdx.x + 256 * i;      // 512 write slots (4 k each)
        int n = idx >> 3, kq = (idx & 7) * 4;
        __half2 h0, h1;
        h0.x = __float2half(ts[kq + 0][n]);
        h0.y = __float2half(ts[kq + 1][n]);
        h1.x = __float2half(ts[kq + 2][n]);
        h1.y = __float2half(ts[kq + 3][n]);
        size_t o = ((size_t)e * N + n0 + n) * K + k0 + kq;
        uint2 pk;
        pk.x = *reinterpret_cast<uint32_t*>(&h0);
        pk.y = *reinterpret_cast<uint32_t*>(&h1);
        *reinterpret_cast<uint2*>(Wh + o) = pk;
    }
}

// swizzled smem byte offset within a [rows x 32] fp16 array (64B rows, 4 chunks)
__device__ __forceinline__ uint32_t sw_off(int row, int chunk) {
    return (uint32_t)(row * 64 + ((chunk ^ ((row >> 1) & 3)) << 4));
}

// ---------------- HMMA grouped GEMM (per-CTA tile plan from counts) ----------------
template <int KDIM, int NDIM, bool RELU_H>
__global__ __launch_bounds__(256, 2)
void moe_mma_kernel(const __half* __restrict__ A,
                    const __half* __restrict__ Wh,
                    const float* __restrict__ bias,
                    __half* __restrict__ OutH,
                    float* __restrict__ OutF) {
    extern __shared__ __align__(1024) char smem[];
    // derive (e, m0) from counts — no tile_plan kernel
    const int ty = blockIdx.y;
    int e = -1, m0 = 0, acc_t = 0;
#pragma unroll
    for (int ee = 0; ee < NE; ee++) {
        int c = g_cnt[ee];
        int nt = (c + TM - 1) / TM;
        if (e < 0 && ty < acc_t + nt) { e = ee; m0 = (ty - acc_t) * TM; }
        acc_t += nt;
    }
    if (e < 0) return;
    const int mcnt = g_cnt[e];
    const int n0 = blockIdx.x * TN;
    const int tid = threadIdx.x;
    const uint32_t sb = smem_u32(smem);

    int* rowtok = (int*)(smem + SM_ROWTOK);
    float* bias_s = (float*)(smem + SM_BIAS);
    if (tid < TM) {
        int gm = m0 + tid;
        rowtok[tid] = g_bucket[e][gm < mcnt ? gm : m0];
        bias_s[tid] = bias[(size_t)e * NDIM + n0 + tid];
    }
    __syncthreads();

    // ---- loaders: thread t -> row t>>1, chunks (t&1)*2 + {0,1} ----
    const int ldr = tid >> 1;
    const int ldc = (tid & 1) * 2;
    const int atok = rowtok[ldr];
    const __half* aSrc = A + (size_t)atok * KDIM + ldc * 8;
    const __half* bSrc = Wh + ((size_t)e * NDIM + n0 + ldr) * KDIM + ldc * 8;
    const uint32_t d0 = sw_off(ldr, ldc);
    const uint32_t d1 = sw_off(ldr, ldc + 1);

    constexpr int NST = KDIM / TK;

    auto load_stage = [&](int s) {
        const uint32_t base = sb + SM_STAGE + (s % NSTAGE) * STAGE_BYTES;
        const int k0 = s * TK;
        cp16(base + OFF_AH + d0, aSrc + k0);
        cp16(base + OFF_AH + d1, aSrc + k0 + 8);
        cp16(base + OFF_BH + d0, bSrc + k0);
        cp16(base + OFF_BH + d1, bSrc + k0 + 8);
        cp_commit();
    };

    // ---- mma mapping: 2x4 warp grid, warp tile 64x32 ----
    const int wid = tid >> 5;
    const int lane = tid & 31;
    const int warp_m = wid >> 2;          // 0..1
    const int warp_n = wid & 3;           // 0..3
    const int rA = warp_m * 64 + (lane & 15);
    const int rB = warp_n * 32 + (lane & 15);
    const int csel = lane >> 4;
    const int sA = (rA >> 1) & 3;
    const int sB = (rB >> 1) & 3;

    float acc[4][4][4];
#pragma unroll
    for (int i = 0; i < 4; i++)
#pragma unroll
        for (int j = 0; j < 4; j++)
#pragma unroll
            for (int r = 0; r < 4; r++) acc[i][j][r] = 0.f;

    load_stage(0);
    load_stage(1);
    load_stage(2);

    for (int s = 0; s < NST; s++) {
        if (s >= NST - 3) cp_wait<0>(); else cp_wait<2>();
        __syncthreads();
        if (s + 3 < NST) load_stage(s + 3);

        const uint32_t base = sb + SM_STAGE + (s % NSTAGE) * STAGE_BYTES;
#pragma unroll
        for (int ks = 0; ks < 2; ks++) {
            const int c0 = ks * 2;
            uint32_t ah[4][4], bh[4][2];
#pragma unroll
            for (int mt = 0; mt < 4; mt++) {
                uint32_t ad = base + OFF_AH + (uint32_t)((rA + mt * 16) * 64) +
                              (uint32_t)(((c0 + csel) ^ sA) << 4);
                LDSM4(ah[mt][0], ah[mt][1], ah[mt][2], ah[mt][3], ad);
            }
#pragma unroll
            for (int np = 0; np < 2; np++) {
                uint32_t bd = base + OFF_BH + (uint32_t)((rB + np * 16) * 64) +
                              (uint32_t)(((c0 + csel) ^ sB) << 4);
                uint32_t t0, t1, t2, t3;
                LDSM4(t0, t1, t2, t3, bd);
                bh[2 * np][0] = t0; bh[2 * np + 1][0] = t1;
                bh[2 * np][1] = t2; bh[2 * np + 1][1] = t3;
            }
#pragma unroll
            for (int mt = 0; mt < 4; mt++)
#pragma unroll
                for (int nt = 0; nt < 4; nt++)
                    MMA16816(acc[mt][nt], ah[mt], bh[nt]);
        }
    }

    // ---- epilogue ----
#pragma unroll
    for (int mt = 0; mt < 4; mt++) {
        const int row0 = warp_m * 64 + mt * 16 + (lane >> 2);
#pragma unroll
        for (int h = 0; h < 2; h++) {
            const int lrow = row0 + 8 * h;
            if (m0 + lrow >= mcnt) continue;
            const int tok = rowtok[lrow];
#pragma unroll
            for (int nt = 0; nt < 4; nt++) {
                const int col = warp_n * 32 + nt * 8 + (lane & 3) * 2;
                float v0 = acc[mt][nt][2 * h] + bias_s[col];
                float v1 = acc[mt][nt][2 * h + 1] + bias_s[col + 1];
                const size_t o = (size_t)tok * NDIM + n0 + col;
                if (RELU_H) {
                    v0 = fmaxf(v0, 0.f);
                    v1 = fmaxf(v1, 0.f);
                    __half2 hv;
                    hv.x = __float2half(v0);
                    hv.y = __float2half(v1);
                    *reinterpret_cast<__half2*>(OutH + o) = hv;
                } else {
                    float2 f2 = make_float2(v0, v1);
                    *reinterpret_cast<float2*>(OutF + o) = f2;
                }
            }
        }
    }
}

// ---------------- launch (R13 topology, parallel prologue) ----------------
extern "C" void kernel_launch(void* const* d_in, const int* in_sizes, int n_in,
                              void* d_out, int out_size) {
    const float* x  = (const float*)d_in[0];
    const float* w1 = (const float*)d_in[1];
    const float* b1 = (const float*)d_in[2];
    const float* w2 = (const float*)d_in[3];
    const float* b2 = (const float*)d_in[4];
    const float* gw = (const float*)d_in[5];
    const float* gb = (const float*)d_in[6];
    float* out = (float*)d_out;

    cudaFuncSetAttribute(moe_mma_kernel<DM, DF, true>,
                         cudaFuncAttributeMaxDynamicSharedMemorySize, SMEM_TOTAL);
    cudaFuncSetAttribute(moe_mma_kernel<DF, DM, false>,
                         cudaFuncAttributeMaxDynamicSharedMemorySize, SMEM_TOTAL);

    __half *xh, *hh, *w1h, *w2h;
    cudaGetSymbolAddress((void**)&xh, g_xh);
    cudaGetSymbolAddress((void**)&hh, g_hh);
    cudaGetSymbolAddress((void**)&w1h, g_w1h);
    cudaGetSymbolAddress((void**)&w2h, g_w2h);

    cudaStream_t sA, sB, sC;
    cudaStreamCreateWithFlags(&sA, cudaStreamNonBlocking);
    cudaStreamCreateWithFlags(&sB, cudaStreamNonBlocking);
    cudaStreamCreateWithFlags(&sC, cudaStreamNonBlocking);
    cudaEvent_t evRoot, evX, evW1, evPre, evW2;
    cudaEventCreateWithFlags(&evRoot, cudaEventDisableTiming);
    cudaEventCreateWithFlags(&evX, cudaEventDisableTiming);
    cudaEventCreateWithFlags(&evW1, cudaEventDisableTiming);
    cudaEventCreateWithFlags(&evPre, cudaEventDisableTiming);
    cudaEventCreateWithFlags(&evW2, cudaEventDisableTiming);

    cudaEventRecord(evRoot, 0);
    cudaStreamWaitEvent(sA, evRoot, 0);
    cudaStreamWaitEvent(sB, evRoot, 0);

    // main: routing (no tile_plan — GEMM CTAs derive tiles from counts)
    zero_cnt_kernel<<<1, 32>>>();
    gate_route_kernel<<<(NT * 32 + 255) / 256, 256>>>(x, gw, gb);

    // side A: x conversion  |  side B: w1 conversion (independent, parallel)
    xconv_kernel<<<2048, 256, 0, sA>>>(x, xh, NT * DM / 4);
    cudaEventRecord(evX, sA);
    wconv_kernel<<<dim3(DF / 64, DM / 32, NE), 256, 0, sB>>>(w1, w1h, DM, DF);
    cudaEventRecord(evW1, sB);

    // GEMM1 waits on gate (program order) + xconv + wconv1
    cudaStreamWaitEvent(0, evX, 0);
    cudaStreamWaitEvent(0, evW1, 0);
    cudaEventRecord(evPre, 0);
    moe_mma_kernel<DM, DF, true>
        <<<dim3(DF / TN, MAXTILES, 1), 256, SMEM_TOTAL>>>(xh, w1h, b1, hh, nullptr);

    // side C: wconv2 starts WITH GEMM1 (hides under its idle DRAM)
    cudaStreamWaitEvent(sC, evPre, 0);
    wconv_kernel<<<dim3(DM / 64, DF / 32, NE), 256, 0, sC>>>(w2, w2h, DF, DM);
    cudaEventRecord(evW2, sC);

    // GEMM2: out = h @ w2 + b2
    cudaStreamWaitEvent(0, evW2, 0);
    moe_mma_kernel<DF, DM, false>
        <<<dim3(DM / TN, MAXTILES, 1), 256, SMEM_TOTAL>>>(hh, w2h, b2, nullptr, out);

    cudaEventDestroy(evRoot);
    cudaEventDestroy(evX);
    cudaEventDestroy(evW1);
    cudaEventDestroy(evPre);
    cudaEventDestroy(evW2);
    cudaStreamDestroy(sA);
    cudaStreamDestroy(sB);
    cudaStreamDestroy(sC);
}